// round 6
// baseline (speedup 1.0000x reference)
#include <cuda_runtime.h>
#include <cuda_bf16.h>
#include <float.h>

// ROI pooling: crop_and_resize (bilinear, 14x14) + 2x2 max pool -> (N,7,7,512)
// feature_map: (1, 50, 75, 512) fp32 NHWC ; rois: (N,4) [x1,y1,x2,y2] ; img_size: (2,) int32
//
// grid = (N, 4): each block handles a PAIR of pooled rows (last block: row 6 only),
// block = 128 threads (one float4 of channels per thread).
// The 4 crop rows of the pair are processed as a reuse chain: per crop row t the
// floor/ceil feature-row horizontal lerps are reused from the previous crop row
// whenever the feature rows coincide (block-uniform flags, predicated loads).
// Validity mask folded into scalar weights.

#define FH 50
#define FW 75
#define FC 512
#define NPOOL 7
#define CROPDIM 14
#define C4 (FC / 4)
#define ROWSTRIDE (FW * C4)

__device__ __forceinline__ float4 hlerp4(const float4 a, const float4 b,
                                         const float wa, const float wb) {
    float4 h;
    h.x = fmaf(b.x, wb, a.x * wa);
    h.y = fmaf(b.y, wb, a.y * wa);
    h.z = fmaf(b.z, wb, a.z * wa);
    h.w = fmaf(b.w, wb, a.w * wa);
    return h;
}

__device__ __forceinline__ float4 vlerp4(const float4 a, const float4 b,
                                         const float wa, const float wb) {
    return hlerp4(a, b, wa, wb);
}

__device__ __forceinline__ void max4(float4& m, const float4 v) {
    m.x = fmaxf(m.x, v.x);
    m.y = fmaxf(m.y, v.y);
    m.z = fmaxf(m.z, v.z);
    m.w = fmaxf(m.w, v.w);
}

__global__ __launch_bounds__(128) void roi_pool_kernel(
    const float* __restrict__ fmap,
    const float* __restrict__ rois,
    const int*   __restrict__ img_size,
    float*       __restrict__ out)
{
    const int n  = blockIdx.x;   // roi index
    const int pp = blockIdx.y;   // pooled-row pair 0..3 (pp=3 -> single row 6)
    const int c4 = threadIdx.x;  // float4 channel chunk 0..127
    const bool twoRows = (pp < 3);

    // ---- uniform per-block scalar setup ----
    const float ih = (float)img_size[0] - 1.0f;   // 799
    const float iw = (float)img_size[1] - 1.0f;   // 1199
    const float4 r = reinterpret_cast<const float4*>(rois)[n]; // x1,y1,x2,y2
    const float bx1 = r.x / iw;
    const float by1 = r.y / ih;
    const float bx2 = r.z / iw;
    const float by2 = r.w / ih;

    const float fh = (float)(FH - 1);   // 49
    const float fw = (float)(FW - 1);   // 74
    const float sy = (by2 - by1) * fh * (1.0f / (CROPDIM - 1));
    const float sx = (bx2 - bx1) * fw * (1.0f / (CROPDIM - 1));
    const float yb = by1 * fh;
    const float xb = bx1 * fw;

    // ---- 4 crop rows of this pooled-row pair (uniform scalars) ----
    int   rowA[4], rowB[4];
    float wyg[4], omwyg[4];
#pragma unroll
    for (int t = 0; t < 4; t++) {
        const float ys = fmaf((float)(4 * pp + t), sy, yb);
        const float gy = ((ys >= 0.0f) && (ys <= fh)) ? 1.0f : 0.0f;
        const float fl = floorf(ys);
        const float wy = ys - fl;
        int yi = min(max((int)fl, 0), FH - 1);
        rowA[t] = yi * ROWSTRIDE;
        rowB[t] = min(yi + 1, FH - 1) * ROWSTRIDE;
        wyg[t]   = wy * gy;
        omwyg[t] = (1.0f - wy) * gy;
    }
    // reuse flags (block-uniform)
    bool fAA[4], fAB[4], fBB[4], fBA[4];
#pragma unroll
    for (int t = 1; t < 4; t++) {
        fAA[t] = (rowA[t] == rowA[t - 1]);   // hA_t = prev hA
        fAB[t] = (rowA[t] == rowB[t - 1]);   // hA_t = prev hB
        fBB[t] = (rowB[t] == rowB[t - 1]);   // hB_t = prev hB
        fBA[t] = (rowB[t] == rowA[t]);       // hB_t = hA_t (clip at bottom edge)
    }

    const float4* __restrict__ fb = reinterpret_cast<const float4*>(fmap) + c4;
    float4* __restrict__ ob0 = reinterpret_cast<float4*>(out)
        + ((long)n * (NPOOL * NPOOL) + (2 * pp) * NPOOL) * C4 + c4;
    float4* __restrict__ ob1 = ob0 + NPOOL * C4;

    for (int px = 0; px < NPOOL; px++) {
        float4 m0 = make_float4(-FLT_MAX, -FLT_MAX, -FLT_MAX, -FLT_MAX);
        float4 m1 = m0;
#pragma unroll
        for (int i = 0; i < 2; i++) {
            const float xs = fmaf((float)(2 * px + i), sx, xb);
            const float gx = ((xs >= 0.0f) && (xs <= fw)) ? 1.0f : 0.0f;
            const float x0 = floorf(xs);
            const float wx = xs - x0;
            int xi = min(max((int)x0, 0), FW - 1);
            const int cA = xi * C4;
            const int cB = min(xi + 1, FW - 1) * C4;
            const float wxg   = wx * gx;
            const float omwxg = (1.0f - wx) * gx;

            // ---- t = 0 ----
            float4 hA = hlerp4(__ldg(fb + rowA[0] + cA), __ldg(fb + rowA[0] + cB),
                               omwxg, wxg);
            float4 hB = hlerp4(__ldg(fb + rowB[0] + cA), __ldg(fb + rowB[0] + cB),
                               omwxg, wxg);
            max4(m0, vlerp4(hA, hB, omwyg[0], wyg[0]));

            // ---- t = 1..3 chain with reuse ----
#pragma unroll
            for (int t = 1; t < 4; t++) {
                const bool active = (t < 2) || twoRows;
                float4 nA, nB;
                if (active) {
                    if (fAA[t])      nA = hA;
                    else if (fAB[t]) nA = hB;
                    else             nA = hlerp4(__ldg(fb + rowA[t] + cA),
                                                 __ldg(fb + rowA[t] + cB),
                                                 omwxg, wxg);
                    if (fBB[t] && !fAA[t] && false) {}  // placeholder (see below)
                    if (fAA[t])      nB = hB;            // same cell -> both reused
                    else if (fBA[t]) nB = nA;            // clipped at bottom
                    else             nB = hlerp4(__ldg(fb + rowB[t] + cA),
                                                 __ldg(fb + rowB[t] + cB),
                                                 omwxg, wxg);
                    const float4 v = vlerp4(nA, nB, omwyg[t], wyg[t]);
                    if (t < 2) max4(m0, v); else max4(m1, v);
                    hA = nA; hB = nB;
                }
            }
        }
        ob0[px * C4] = m0;
        if (twoRows) ob1[px * C4] = m1;
    }
}

extern "C" void kernel_launch(void* const* d_in, const int* in_sizes, int n_in,
                              void* d_out, int out_size) {
    const float* fmap     = (const float*)d_in[0];
    const float* rois     = (const float*)d_in[1];
    const int*   img_size = (const int*)d_in[2];
    float* out = (float*)d_out;

    const int N = in_sizes[1] / 4;   // number of rois
    dim3 grid(N, 4);
    roi_pool_kernel<<<grid, 128>>>(fmap, rois, img_size, out);
}

// round 7
// speedup vs baseline: 1.0513x; 1.0513x over previous
#include <cuda_runtime.h>
#include <cuda_bf16.h>
#include <float.h>

// ROI pooling: crop_and_resize (bilinear, 14x14) + 2x2 max pool -> (N,7,7,512)
// feature_map: (1, 50, 75, 512) fp32 NHWC ; rois: (N,4) [x1,y1,x2,y2] ; img_size: (2,) int32
//
// grid = (N, 7 pooled rows), block = 128 threads (one float4 of channels per thread).
// The block-uniform "shared middle feature row" condition (rowB[0]==rowT[1], ~70%)
// is hoisted OUT of the px loop into two specialized straight-line paths so that
// all LDG.128 of a (px,i) sample issue independently and front-batched.
// Validity mask folded into scalar weights.

#define FH 50
#define FW 75
#define FC 512
#define NPOOL 7
#define CROPDIM 14
#define C4 (FC / 4)
#define ROWSTRIDE (FW * C4)

__device__ __forceinline__ float4 lerp4(const float4 a, const float4 b,
                                        const float wa, const float wb) {
    float4 h;
    h.x = fmaf(b.x, wb, a.x * wa);
    h.y = fmaf(b.y, wb, a.y * wa);
    h.z = fmaf(b.z, wb, a.z * wa);
    h.w = fmaf(b.w, wb, a.w * wa);
    return h;
}

__device__ __forceinline__ float4 max4(const float4 a, const float4 b) {
    float4 m;
    m.x = fmaxf(a.x, b.x);
    m.y = fmaxf(a.y, b.y);
    m.z = fmaxf(a.z, b.z);
    m.w = fmaxf(a.w, b.w);
    return m;
}

struct XCol {
    int   cA, cB;
    float wxg, omwxg;
};

__device__ __forceinline__ XCol xcol(const int k, const float sx, const float xb,
                                     const float fw) {
    XCol c;
    const float xs = fmaf((float)k, sx, xb);
    const float gx = ((xs >= 0.0f) && (xs <= fw)) ? 1.0f : 0.0f;
    const float x0 = floorf(xs);
    const float wx = xs - x0;
    int xi = min(max((int)x0, 0), FW - 1);
    c.cA = xi * C4;
    c.cB = min(xi + 1, FW - 1) * C4;
    c.wxg   = wx * gx;
    c.omwxg = (1.0f - wx) * gx;
    return c;
}

__global__ __launch_bounds__(128) void roi_pool_kernel(
    const float* __restrict__ fmap,
    const float* __restrict__ rois,
    const int*   __restrict__ img_size,
    float*       __restrict__ out)
{
    const int n  = blockIdx.x;   // roi index
    const int py = blockIdx.y;   // pooled row 0..6
    const int c4 = threadIdx.x;  // float4 channel chunk 0..127

    // ---- uniform per-block scalar setup ----
    const float ih = (float)img_size[0] - 1.0f;   // 799
    const float iw = (float)img_size[1] - 1.0f;   // 1199
    const float4 r = reinterpret_cast<const float4*>(rois)[n]; // x1,y1,x2,y2
    const float bx1 = r.x / iw;
    const float by1 = r.y / ih;
    const float bx2 = r.z / iw;
    const float by2 = r.w / ih;

    const float fh = (float)(FH - 1);   // 49
    const float fw = (float)(FW - 1);   // 74
    const float sy = (by2 - by1) * fh * (1.0f / (CROPDIM - 1));
    const float sx = (bx2 - bx1) * fw * (1.0f / (CROPDIM - 1));
    const float yb = by1 * fh;
    const float xb = bx1 * fw;

    // two crop rows feeding this pooled row (uniform scalars)
    int   row0, row1, row2, row3;
    float wyg0, omwyg0, wyg1, omwyg1;
    {
        const float ys0 = fmaf((float)(2 * py), sy, yb);
        const float gy0 = ((ys0 >= 0.0f) && (ys0 <= fh)) ? 1.0f : 0.0f;
        const float fl0 = floorf(ys0);
        const float wy0 = ys0 - fl0;
        int yi0 = min(max((int)fl0, 0), FH - 1);
        row0 = yi0 * ROWSTRIDE;
        row1 = min(yi0 + 1, FH - 1) * ROWSTRIDE;
        wyg0 = wy0 * gy0;  omwyg0 = (1.0f - wy0) * gy0;

        const float ys1 = fmaf((float)(2 * py + 1), sy, yb);
        const float gy1 = ((ys1 >= 0.0f) && (ys1 <= fh)) ? 1.0f : 0.0f;
        const float fl1 = floorf(ys1);
        const float wy1 = ys1 - fl1;
        int yi1 = min(max((int)fl1, 0), FH - 1);
        row2 = yi1 * ROWSTRIDE;
        row3 = min(yi1 + 1, FH - 1) * ROWSTRIDE;
        wyg1 = wy1 * gy1;  omwyg1 = (1.0f - wy1) * gy1;
    }

    const float4* __restrict__ fb = reinterpret_cast<const float4*>(fmap) + c4;
    float4* __restrict__ ob = reinterpret_cast<float4*>(out)
        + ((long)n * (NPOOL * NPOOL) + py * NPOOL) * C4 + c4;

    if (row2 == row1) {
        // ---- shared middle feature row: 3 distinct rows, 6 loads per sample ----
#pragma unroll
        for (int px = 0; px < NPOOL; px++) {
            float4 v[2][2];
#pragma unroll
            for (int i = 0; i < 2; i++) {
                const XCol c = xcol(2 * px + i, sx, xb, fw);
                const float4 a0 = __ldg(fb + row0 + c.cA);
                const float4 b0 = __ldg(fb + row0 + c.cB);
                const float4 a1 = __ldg(fb + row1 + c.cA);
                const float4 b1 = __ldg(fb + row1 + c.cB);
                const float4 a3 = __ldg(fb + row3 + c.cA);
                const float4 b3 = __ldg(fb + row3 + c.cB);
                const float4 h0 = lerp4(a0, b0, c.omwxg, c.wxg);
                const float4 h1 = lerp4(a1, b1, c.omwxg, c.wxg);
                const float4 h3 = lerp4(a3, b3, c.omwxg, c.wxg);
                v[i][0] = lerp4(h0, h1, omwyg0, wyg0);
                v[i][1] = lerp4(h1, h3, omwyg1, wyg1);
            }
            ob[px * C4] = max4(max4(v[0][0], v[0][1]), max4(v[1][0], v[1][1]));
        }
    } else {
        // ---- generic: 4 distinct rows, 8 loads per sample ----
#pragma unroll
        for (int px = 0; px < NPOOL; px++) {
            float4 v[2][2];
#pragma unroll
            for (int i = 0; i < 2; i++) {
                const XCol c = xcol(2 * px + i, sx, xb, fw);
                const float4 a0 = __ldg(fb + row0 + c.cA);
                const float4 b0 = __ldg(fb + row0 + c.cB);
                const float4 a1 = __ldg(fb + row1 + c.cA);
                const float4 b1 = __ldg(fb + row1 + c.cB);
                const float4 a2 = __ldg(fb + row2 + c.cA);
                const float4 b2 = __ldg(fb + row2 + c.cB);
                const float4 a3 = __ldg(fb + row3 + c.cA);
                const float4 b3 = __ldg(fb + row3 + c.cB);
                const float4 h0 = lerp4(a0, b0, c.omwxg, c.wxg);
                const float4 h1 = lerp4(a1, b1, c.omwxg, c.wxg);
                const float4 h2 = lerp4(a2, b2, c.omwxg, c.wxg);
                const float4 h3 = lerp4(a3, b3, c.omwxg, c.wxg);
                v[i][0] = lerp4(h0, h1, omwyg0, wyg0);
                v[i][1] = lerp4(h2, h3, omwyg1, wyg1);
            }
            ob[px * C4] = max4(max4(v[0][0], v[0][1]), max4(v[1][0], v[1][1]));
        }
    }
}

extern "C" void kernel_launch(void* const* d_in, const int* in_sizes, int n_in,
                              void* d_out, int out_size) {
    const float* fmap     = (const float*)d_in[0];
    const float* rois     = (const float*)d_in[1];
    const int*   img_size = (const int*)d_in[2];
    float* out = (float*)d_out;

    const int N = in_sizes[1] / 4;   // number of rois
    dim3 grid(N, NPOOL);
    roi_pool_kernel<<<grid, 128>>>(fmap, rois, img_size, out);
}